// round 12
// baseline (speedup 1.0000x reference)
#include <cuda_runtime.h>

#define Nn 384
#define Dm 256
#define MARGIN 0.2f
#define ANCH 3
#define NBLK (Nn / ANCH)      // 128
#define NTHR 768
#define NWARP 24
#define RPR 96                // rows per round = 24 warps * 4 j
#define NROUND 4              // 384 / 96

// dynamic smem layout (bytes)
#define STAGE_BYTES   (RPR * Dm * 4)            // 98304 per stage
#define OFF_STAGE     0
#define OFF_EA        (2 * STAGE_BYTES)         // 196608
#define OFF_DROW      (OFF_EA + ANCH * 64 * 16) // 199680
#define OFF_SSSQ      (OFF_DROW + ANCH * Nn * 4)// 204288
#define OFF_SLAB      (OFF_SSSQ + Nn * 4)       // 205824
#define OFF_PD        (OFF_SLAB + Nn * 4)       // 207360
#define OFF_WCNT      (OFF_PD + Nn * 4)         // 208896
#define OFF_RSUM      (OFF_WCNT + NWARP * 4)    // 208992
#define OFF_RCNT      (OFF_RSUM + NWARP * 4)    // 209088
#define OFF_SLAST     (OFF_RCNT + NWARP * 4)    // 209184
#define SMEM_TOTAL    (OFF_SLAST + 16)          // 209200

typedef unsigned long long u64;

__device__ float    g_psum[NBLK];
__device__ int      g_pcnt[NBLK];
__device__ unsigned g_flag;      // zero-init; last block resets to 0 each run

__device__ __forceinline__ u64 ffma2(u64 a, u64 b, u64 c) {
    u64 d;
    asm("fma.rn.f32x2 %0, %1, %2, %3;" : "=l"(d) : "l"(a), "l"(b), "l"(c));
    return d;
}
__device__ __forceinline__ float hadd2(u64 p) {
    float lo, hi;
    asm("mov.b64 {%0, %1}, %2;" : "=f"(lo), "=f"(hi) : "l"(p));
    return lo + hi;
}

__global__ void __launch_bounds__(NTHR, 1)
k_fused(const float* __restrict__ e, const int* __restrict__ lab,
        float* __restrict__ out) {
    extern __shared__ char smem[];
    ulonglong2* stage = (ulonglong2*)(smem + OFF_STAGE);   // 2 x 6144 entries
    ulonglong2* ea    = (ulonglong2*)(smem + OFF_EA);      // 192 entries
    float (*Drow)[Nn] = (float(*)[Nn])(smem + OFF_DROW);
    float* sssq = (float*)(smem + OFF_SSSQ);
    int*   slab = (int*)(smem + OFF_SLAB);
    float* pd   = (float*)(smem + OFF_PD);
    int*   wcnt = (int*)(smem + OFF_WCNT);
    float* rsum = (float*)(smem + OFF_RSUM);
    int*   rcnt = (int*)(smem + OFF_RCNT);
    int*   s_last = (int*)(smem + OFF_SLAST);

    const int t = threadIdx.x, w = t >> 5, lane = t & 31;
    const int a0 = blockIdx.x * ANCH;
    const unsigned smem_u32 = (unsigned)__cvta_generic_to_shared(smem);

    // async stage loader: 6144 16B chunks per stage, 8 per thread
    auto load_stage = [&](int buf, int rowbase) {
        unsigned dst0 = smem_u32 + OFF_STAGE + buf * STAGE_BYTES + t * 16;
        const char* src0 = (const char*)e + rowbase * (Dm * 4) + t * 16;
        #pragma unroll
        for (int k = 0; k < 8; k++) {
            asm volatile("cp.async.cg.shared.global [%0], [%1], 16;"
                         :: "r"(dst0 + k * (NTHR * 16)), "l"(src0 + k * (NTHR * 16)));
        }
        asm volatile("cp.async.commit_group;");
    };

    // kick off stage 0 immediately
    load_stage(0, 0);

    // anchors + labels via plain loads (covered by the first barrier)
    if (t < Nn) slab[t] = lab[t];
    if (t < ANCH * 64) ea[t] = ((const ulonglong2*)(e + a0 * Dm))[t];

    // ---- Phase 2: 4 double-buffered rounds, 8 lanes per j, 4 j's per warp ----
    const int jj = lane >> 3;
    const int kk = lane & 7;
    const int lrow = w * 4 + jj;          // row within stage (0..95)

    #pragma unroll
    for (int r = 0; r < NROUND; r++) {
        if (r + 1 < NROUND) load_stage((r + 1) & 1, (r + 1) * RPR);
        if (r + 1 < NROUND) { asm volatile("cp.async.wait_group 1;"); }
        else                { asm volatile("cp.async.wait_group 0;"); }
        __syncthreads();                  // stage r ready for everyone (and ea/slab on r=0)

        const ulonglong2* __restrict__ st = stage + (r & 1) * (RPR * 64) + lrow * 64;
        u64 qp = 0ull, s0 = 0ull, s1 = 0ull, s2 = 0ull;
        #pragma unroll
        for (int c = 0; c < 8; c++) {
            const int f = kk + 8 * c;
            ulonglong2 vv = st[f];
            ulonglong2 b0 = ea[0 * 64 + f];
            ulonglong2 b1 = ea[1 * 64 + f];
            ulonglong2 b2 = ea[2 * 64 + f];
            qp = ffma2(vv.x, vv.x, qp); qp = ffma2(vv.y, vv.y, qp);
            s0 = ffma2(b0.x, vv.x, s0); s0 = ffma2(b0.y, vv.y, s0);
            s1 = ffma2(b1.x, vv.x, s1); s1 = ffma2(b1.y, vv.y, s1);
            s2 = ffma2(b2.x, vv.x, s2); s2 = ffma2(b2.y, vv.y, s2);
        }
        float q  = hadd2(qp);
        float c0 = hadd2(s0);
        float c1 = hadd2(s1);
        float c2 = hadd2(s2);
        #pragma unroll
        for (int o = 1; o < 8; o <<= 1) {
            q  += __shfl_xor_sync(0xffffffffu, q,  o);
            c0 += __shfl_xor_sync(0xffffffffu, c0, o);
            c1 += __shfl_xor_sync(0xffffffffu, c1, o);
            c2 += __shfl_xor_sync(0xffffffffu, c2, o);
        }
        if (kk == 0) {
            const int j = r * RPR + lrow;
            sssq[j]    = q;
            Drow[0][j] = c0;
            Drow[1][j] = c1;
            Drow[2][j] = c2;
        }
        __syncthreads();                  // stage (r&1) free before round r+1 overwrites it
    }

    // ---- Parallel epilogue: raw dot -> distance, thread t = column j ----
    if (t < Nn) {
        float sj = rsqrtf(fmaxf(sssq[t], 1e-24f));
        #pragma unroll
        for (int aa = 0; aa < ANCH; aa++) {
            float sa = rsqrtf(fmaxf(sssq[a0 + aa], 1e-24f));
            float d2 = 2.0f - 2.0f * Drow[aa][t] * sa * sj;
            d2 = fmaxf(d2, 0.0f);
            Drow[aa][t] = (d2 > 0.0f) ? sqrtf(d2) : 0.0f;
        }
    }
    __syncthreads();

    // ---- Phase 3+4: per anchor, ballot-compaction of positives + negative scan ----
    float lsum = 0.0f;
    int   lcnt = 0;
    #pragma unroll
    for (int aa = 0; aa < ANCH; aa++) {
        const int a  = a0 + aa;
        const int la = slab[a];
        bool isp = (t < Nn) && (slab[t] == la) && (t != a);
        unsigned m = __ballot_sync(0xffffffffu, isp);
        if (lane == 0) wcnt[w] = __popc(m);
        __syncthreads();
        int off = 0, npos = 0;
        #pragma unroll
        for (int i = 0; i < NWARP; i++) {
            int c = wcnt[i];
            if (i < w) off += c;
            npos += c;
        }
        if (isp) pd[off + __popc(m & ((1u << lane) - 1u))] = Drow[aa][t];
        __syncthreads();

        if (t < Nn && slab[t] != la) {
            float dn = Drow[aa][t];
            for (int i = 0; i < npos; i++) {
                float tm = dn - pd[i];
                // semihard & loss>0  <=>  0 < tm < MARGIN (tm==MARGIN adds 0)
                if (tm > 0.0f && tm < MARGIN) { lsum += (MARGIN - tm); lcnt++; }
            }
        }
        __syncthreads();
    }

    // ---- Block reduction (fixed order, deterministic) ----
    #pragma unroll
    for (int o = 16; o > 0; o >>= 1) {
        lsum += __shfl_xor_sync(0xffffffffu, lsum, o);
        lcnt += __shfl_xor_sync(0xffffffffu, lcnt, o);
    }
    if (lane == 0) { rsum[w] = lsum; rcnt[w] = lcnt; }
    __syncthreads();
    if (t == 0) {
        float s = 0.0f; int c = 0;
        #pragma unroll
        for (int i = 0; i < NWARP; i++) { s += rsum[i]; c += rcnt[i]; }
        g_psum[blockIdx.x] = s;
        g_pcnt[blockIdx.x] = c;
        __threadfence();
        unsigned old = atomicAdd(&g_flag, 1u);
        s_last[0] = (old == NBLK - 1) ? 1 : 0;
    }
    __syncthreads();

    // ---- Last block folds the 128 partials (deterministic order) ----
    if (s_last[0]) {
        float s2 = (t < NBLK) ? g_psum[t] : 0.0f;
        int   c2 = (t < NBLK) ? g_pcnt[t] : 0;
        #pragma unroll
        for (int o = 16; o > 0; o >>= 1) {
            s2 += __shfl_xor_sync(0xffffffffu, s2, o);
            c2 += __shfl_xor_sync(0xffffffffu, c2, o);
        }
        if (lane == 0 && w < 4) { rsum[w] = s2; rcnt[w] = c2; }
        __syncthreads();
        if (t == 0) {
            float ts = rsum[0] + rsum[1] + rsum[2] + rsum[3];
            int   tc = rcnt[0] + rcnt[1] + rcnt[2] + rcnt[3];
            out[0] = (tc > 0) ? (ts / (float)tc) : 0.0f;
            g_flag = 0;   // reset for next graph replay
        }
    }
}

extern "C" void kernel_launch(void* const* d_in, const int* in_sizes, int n_in,
                              void* d_out, int out_size) {
    const float* e   = (const float*)d_in[0];
    const int*   lab = (const int*)d_in[1];
    cudaFuncSetAttribute(k_fused, cudaFuncAttributeMaxDynamicSharedMemorySize, SMEM_TOTAL);
    k_fused<<<NBLK, NTHR, SMEM_TOTAL>>>(e, lab, (float*)d_out);
}

// round 13
// speedup vs baseline: 1.3193x; 1.3193x over previous
#include <cuda_runtime.h>

#define Nn 384
#define Dm 256
#define MARGIN 0.2f
#define ANCH 3
#define NBLK (Nn / ANCH)   // 128
#define NTHR 384
#define NWARP 12
#define JSTEP (NWARP * 8)  // 96 j's per round, 4 rounds

typedef unsigned long long u64;

__device__ float    g_psum[NBLK];
__device__ int      g_pcnt[NBLK];
__device__ unsigned g_flag;      // zero-init; last block resets to 0 each run

__device__ __forceinline__ u64 ffma2(u64 a, u64 b, u64 c) {
    u64 d;
    asm("fma.rn.f32x2 %0, %1, %2, %3;" : "=l"(d) : "l"(a), "l"(b), "l"(c));
    return d;
}
__device__ __forceinline__ float hadd2(u64 p) {
    float lo, hi;
    asm("mov.b64 {%0, %1}, %2;" : "=f"(lo), "=f"(hi) : "l"(p));
    return lo + hi;
}

__global__ void __launch_bounds__(NTHR, 1)
k_fused(const float* __restrict__ e, const int* __restrict__ lab,
        float* __restrict__ out) {
    __shared__ ulonglong2 ea[ANCH * 64];  // raw anchor rows (packed f32x2 pairs)
    __shared__ float  Drow[ANCH][Nn];     // raw dots -> distances (in place)
    __shared__ float  sssq[Nn];           // raw squared norms per j
    __shared__ int    slab[Nn];
    __shared__ float  pd[Nn];             // compacted positive distances
    __shared__ int    wcnt[NWARP];
    __shared__ float  rsum[NWARP];
    __shared__ int    rcnt[NWARP];
    __shared__ int    s_last;

    const int t = threadIdx.x, w = t >> 5, lane = t & 31;
    const int a0 = blockIdx.x * ANCH;

    if (t < Nn) slab[t] = lab[t];
    {
        const ulonglong2* src = (const ulonglong2*)(e + a0 * Dm);
        if (t < ANCH * 64) ea[t] = src[t];
    }
    __syncthreads();

    // ---- Phase 2: 8 lanes per j, TWO j-groups per iteration sharing anchor loads ----
    const int jj = lane >> 3;            // which j within a group of 4
    const int kk = lane & 7;             // k-slice (8 x 16B per lane)

    // anchor 0 slice hoisted to registers (16 regs)
    ulonglong2 r0[8];
    #pragma unroll
    for (int c = 0; c < 8; c++) r0[c] = ea[0 * 64 + kk + 8 * c];

    ulonglong2 vA[8];
    {
        const ulonglong2* __restrict__ row = (const ulonglong2*)(e + (w * 8 + jj) * Dm);
        #pragma unroll
        for (int c = 0; c < 8; c++) vA[c] = row[kk + 8 * c];
    }

    #pragma unroll 1
    for (int jb = w * 8; jb < Nn; jb += JSTEP) {       // 4 iterations
        // load group B rows (jb+4+jj)
        ulonglong2 vB[8];
        {
            const ulonglong2* __restrict__ rowB = (const ulonglong2*)(e + (jb + 4 + jj) * Dm);
            #pragma unroll
            for (int c = 0; c < 8; c++) vB[c] = rowB[kk + 8 * c];
        }

        u64 qpA = 0ull, a0p = 0ull, a1p = 0ull, a2p = 0ull;
        u64 qpB = 0ull, b0p = 0ull, b1p = 0ull, b2p = 0ull;
        // fused c-loop: anchor loads shared by both j-groups
        #pragma unroll
        for (int c = 0; c < 8; c++) {
            const int f = kk + 8 * c;
            ulonglong2 e0 = r0[c];
            ulonglong2 e1 = ea[1 * 64 + f];
            ulonglong2 e2 = ea[2 * 64 + f];
            ulonglong2 va = vA[c];
            ulonglong2 vb = vB[c];
            qpA = ffma2(va.x, va.x, qpA); qpA = ffma2(va.y, va.y, qpA);
            qpB = ffma2(vb.x, vb.x, qpB); qpB = ffma2(vb.y, vb.y, qpB);
            a0p = ffma2(e0.x, va.x, a0p); a0p = ffma2(e0.y, va.y, a0p);
            b0p = ffma2(e0.x, vb.x, b0p); b0p = ffma2(e0.y, vb.y, b0p);
            a1p = ffma2(e1.x, va.x, a1p); a1p = ffma2(e1.y, va.y, a1p);
            b1p = ffma2(e1.x, vb.x, b1p); b1p = ffma2(e1.y, vb.y, b1p);
            a2p = ffma2(e2.x, va.x, a2p); a2p = ffma2(e2.y, va.y, a2p);
            b2p = ffma2(e2.x, vb.x, b2p); b2p = ffma2(e2.y, vb.y, b2p);
        }

        // prefetch next iteration's group A rows (wraps harmlessly on last iter)
        {
            const int jbn = (jb + JSTEP < Nn) ? (jb + JSTEP) : 0;
            const ulonglong2* __restrict__ rown = (const ulonglong2*)(e + (jbn + jj) * Dm);
            #pragma unroll
            for (int c = 0; c < 8; c++) vA[c] = rown[kk + 8 * c];
        }

        // 8 independent reduction chains
        float qA  = hadd2(qpA), c0A = hadd2(a0p), c1A = hadd2(a1p), c2A = hadd2(a2p);
        float qB  = hadd2(qpB), c0B = hadd2(b0p), c1B = hadd2(b1p), c2B = hadd2(b2p);
        #pragma unroll
        for (int o = 1; o < 8; o <<= 1) {
            qA  += __shfl_xor_sync(0xffffffffu, qA,  o);
            qB  += __shfl_xor_sync(0xffffffffu, qB,  o);
            c0A += __shfl_xor_sync(0xffffffffu, c0A, o);
            c0B += __shfl_xor_sync(0xffffffffu, c0B, o);
            c1A += __shfl_xor_sync(0xffffffffu, c1A, o);
            c1B += __shfl_xor_sync(0xffffffffu, c1B, o);
            c2A += __shfl_xor_sync(0xffffffffu, c2A, o);
            c2B += __shfl_xor_sync(0xffffffffu, c2B, o);
        }
        if (kk == 0) {
            const int jA = jb + jj, jBx = jb + 4 + jj;
            sssq[jA]    = qA;   sssq[jBx]    = qB;
            Drow[0][jA] = c0A;  Drow[0][jBx] = c0B;
            Drow[1][jA] = c1A;  Drow[1][jBx] = c1B;
            Drow[2][jA] = c2A;  Drow[2][jBx] = c2B;
        }
    }
    __syncthreads();

    // ---- Parallel epilogue: raw dot -> distance, thread t = column j ----
    {
        float sj = rsqrtf(fmaxf(sssq[t], 1e-24f));
        #pragma unroll
        for (int aa = 0; aa < ANCH; aa++) {
            float sa = rsqrtf(fmaxf(sssq[a0 + aa], 1e-24f));
            float d2 = 2.0f - 2.0f * Drow[aa][t] * sa * sj;
            d2 = fmaxf(d2, 0.0f);
            Drow[aa][t] = (d2 > 0.0f) ? sqrtf(d2) : 0.0f;
        }
    }
    __syncthreads();

    // ---- Phase 3+4: per anchor, ballot-compaction of positives + negative scan ----
    float lsum = 0.0f;
    int   lcnt = 0;
    #pragma unroll
    for (int aa = 0; aa < ANCH; aa++) {
        const int a  = a0 + aa;
        const int la = slab[a];
        bool isp = (slab[t] == la) && (t != a);
        unsigned m = __ballot_sync(0xffffffffu, isp);
        if (lane == 0) wcnt[w] = __popc(m);
        __syncthreads();
        int off = 0, npos = 0;
        #pragma unroll
        for (int i = 0; i < NWARP; i++) {
            int c = wcnt[i];
            if (i < w) off += c;
            npos += c;
        }
        if (isp) pd[off + __popc(m & ((1u << lane) - 1u))] = Drow[aa][t];
        __syncthreads();

        if (slab[t] != la) {
            float dn = Drow[aa][t];
            for (int i = 0; i < npos; i++) {
                float tm = dn - pd[i];
                // semihard & loss>0  <=>  0 < tm < MARGIN (tm==MARGIN adds 0)
                if (tm > 0.0f && tm < MARGIN) { lsum += (MARGIN - tm); lcnt++; }
            }
        }
        __syncthreads();
    }

    // ---- Block reduction (fixed order, deterministic) ----
    #pragma unroll
    for (int o = 16; o > 0; o >>= 1) {
        lsum += __shfl_xor_sync(0xffffffffu, lsum, o);
        lcnt += __shfl_xor_sync(0xffffffffu, lcnt, o);
    }
    if (lane == 0) { rsum[w] = lsum; rcnt[w] = lcnt; }
    __syncthreads();
    if (t == 0) {
        float s = 0.0f; int c = 0;
        #pragma unroll
        for (int i = 0; i < NWARP; i++) { s += rsum[i]; c += rcnt[i]; }
        g_psum[blockIdx.x] = s;
        g_pcnt[blockIdx.x] = c;
        __threadfence();
        unsigned old = atomicAdd(&g_flag, 1u);
        s_last = (old == NBLK - 1) ? 1 : 0;
    }
    __syncthreads();

    // ---- Last block folds the 128 partials (deterministic order) ----
    if (s_last) {
        float s2 = (t < NBLK) ? g_psum[t] : 0.0f;
        int   c2 = (t < NBLK) ? g_pcnt[t] : 0;
        #pragma unroll
        for (int o = 16; o > 0; o >>= 1) {
            s2 += __shfl_xor_sync(0xffffffffu, s2, o);
            c2 += __shfl_xor_sync(0xffffffffu, c2, o);
        }
        if (lane == 0 && w < 4) { rsum[w] = s2; rcnt[w] = c2; }
        __syncthreads();
        if (t == 0) {
            float ts = rsum[0] + rsum[1] + rsum[2] + rsum[3];
            int   tc = rcnt[0] + rcnt[1] + rcnt[2] + rcnt[3];
            out[0] = (tc > 0) ? (ts / (float)tc) : 0.0f;
            g_flag = 0;   // reset for next graph replay
        }
    }
}

extern "C" void kernel_launch(void* const* d_in, const int* in_sizes, int n_in,
                              void* d_out, int out_size) {
    const float* e   = (const float*)d_in[0];
    const int*   lab = (const int*)d_in[1];
    k_fused<<<NBLK, NTHR>>>(e, lab, (float*)d_out);
}